// round 12
// baseline (speedup 1.0000x reference)
#include <cuda_runtime.h>
#include <cuda_bf16.h>

#define VSA_N    2048
#define VSA_BLK  1024          // 32 warps
#define VSA_ROWS 32            // rows per block == lanes; lane owns a row
#define VSA_JSEG (VSA_N / 32)  // 64 j's per warp

// ---------------------------------------------------------------------------
// Fused kernel, TRANSPOSED decomposition. grid = (2048/32, B) = (64, 4),
// 1024 threads (32 warps).
//
//   * lane l owns output row i = bx*32 + l  (private Z,W accumulators)
//   * warp w covers j in [w*64, (w+1)*64)
//   * every lane of a warp reads the SAME sk[j]  -> LDS BROADCAST (N=1)
//
// R11 lesson: unroll 8 wanted 8 float4 = 32 regs for loads alone under the
// (1024,2) 32-reg cap -> ptxas spilled to local (L1=34.5% instead of ~12,
// issue count ~2.5x hand count). This round: unroll 4 (16 regs of loads,
// ~28 total: no spill, still MLP=4) and fabsf instead of fmaxf (folds into
// the MUFU operand; saves the FMNMX alu slot -- |n2|~=0 when cancellation
// goes negative, so e ~= 1 either way).
//
// Phase A: block-redundant means of q,k,v (L2-resident).
// Phase B: stage k' = (k-mk)*c1 as float4 (xyz, |k'|^2), c1 = log2e/sqrt(N).
// Phase C: hot loop (broadcast). ALGEBRA: T_i = q_i x (sum_j e_ij k_j),
//          |q x k|^2 = |q|^2|k|^2 - (q.k)^2, e = ex2(sqrt(n2')) raw MUFUs.
// Phase D: partials -> smem (reusing sk after a sync), warp r reduces row r.
// ---------------------------------------------------------------------------
__global__ __launch_bounds__(VSA_BLK, 2)
void vsa_fused_kernel(const float* __restrict__ q,
                      const float* __restrict__ k,
                      const float* __restrict__ v,
                      float* __restrict__ out) {
    __shared__ float4 sk[VSA_N];           // 32 KB; reused for partials later
    __shared__ float  red[VSA_BLK / 32][9];
    __shared__ float  means[9];

    const int tid  = threadIdx.x;
    const int b    = blockIdx.y;
    const int warp = tid >> 5;
    const int lane = tid & 31;

    const float* qb = q + (size_t)b * VSA_N * 3;
    const float* kb = k + (size_t)b * VSA_N * 3;
    const float* vb = v + (size_t)b * VSA_N * 3;

    // ---- Phase A: per-batch means (block-redundant) ----
    {
        float s[9];
#pragma unroll
        for (int c = 0; c < 9; c++) s[c] = 0.0f;

#pragma unroll
        for (int r = 0; r < VSA_N / VSA_BLK; r++) {
            const int o = (tid + r * VSA_BLK) * 3;
            s[0] += qb[o + 0]; s[1] += qb[o + 1]; s[2] += qb[o + 2];
            s[3] += kb[o + 0]; s[4] += kb[o + 1]; s[5] += kb[o + 2];
            s[6] += vb[o + 0]; s[7] += vb[o + 1]; s[8] += vb[o + 2];
        }
#pragma unroll
        for (int c = 0; c < 9; c++) {
#pragma unroll
            for (int off = 16; off > 0; off >>= 1)
                s[c] += __shfl_xor_sync(0xFFFFFFFFu, s[c], off);
        }
        if (lane == 0) {
#pragma unroll
            for (int c = 0; c < 9; c++) red[warp][c] = s[c];
        }
        __syncthreads();
        if (tid < 9) {
            float t = 0.0f;
#pragma unroll
            for (int w = 0; w < VSA_BLK / 32; w++) t += red[w][tid];
            means[tid] = t * (1.0f / (float)VSA_N);
        }
        __syncthreads();
    }

    const float mqx = means[0], mqy = means[1], mqz = means[2];
    const float mkx = means[3], mky = means[4], mkz = means[5];
    const float mvx = means[6], mvy = means[7], mvz = means[8];

    // c1 = log2(e) / sqrt(2048)
    const float c1 = 1.4426950408889634f * 0.022097086912079612f;

    // ---- Phase B: stage k' (re-read k; L2-hot from phase A) ----
#pragma unroll
    for (int r = 0; r < VSA_N / VSA_BLK; r++) {
        const int j = tid + r * VSA_BLK;
        const float kx = (kb[j * 3 + 0] - mkx) * c1;
        const float ky = (kb[j * 3 + 1] - mky) * c1;
        const float kz = (kb[j * 3 + 2] - mkz) * c1;
        const float kk = fmaf(kx, kx, fmaf(ky, ky, kz * kz));
        sk[j] = make_float4(kx, ky, kz, kk);
    }
    __syncthreads();

    // ---- Phase C: hot loop. Lane l -> row i; warp w -> j segment. ----
    const int i = blockIdx.x * VSA_ROWS + lane;

    const float qx = qb[i * 3 + 0] - mqx;
    const float qy = qb[i * 3 + 1] - mqy;
    const float qz = qb[i * 3 + 2] - mqz;
    const float qq = fmaf(qx, qx, fmaf(qy, qy, qz * qz));

    float Z = 0.0f, Wx = 0.0f, Wy = 0.0f, Wz = 0.0f;

    const float4* pj = sk + warp * VSA_JSEG;
#pragma unroll 4
    for (int jj = 0; jj < VSA_JSEG; jj++) {
        const float4 f = pj[jj];            // broadcast: all lanes same addr
        const float dot = fmaf(qx, f.x, fmaf(qy, f.y, qz * f.z));
        // |n2|: cancellation can go slightly negative only when n2 ~ 0,
        // where |n2| ~ 0 -> e ~ 1 regardless. fabs folds into MUFU operand.
        const float n2 = fabsf(fmaf(-dot, dot, qq * f.w));
        float e;
        asm("sqrt.approx.f32 %0, %1;" : "=f"(e) : "f"(n2));
        asm("ex2.approx.f32 %0, %1;"  : "=f"(e) : "f"(e));
        Z += e;
        Wx = fmaf(e, f.x, Wx);
        Wy = fmaf(e, f.y, Wy);
        Wz = fmaf(e, f.z, Wz);
    }

    // ---- Phase D: cross-warp reduction of per-lane partials ----
    // Reuse sk as float4 part[warp*33 + lane] (padded stride 33).
    __syncthreads();  // all warps done READING sk before we overwrite it
    float4* part = sk;
    part[warp * 33 + lane] = make_float4(Z, Wx, Wy, Wz);
    __syncthreads();

    // Warp r reduces row r: lane l holds warp-l's partial for row r.
    {
        const float4 p = part[lane * 33 + warp];
        float Zr = p.x, Wxr = p.y, Wyr = p.z, Wzr = p.w;
#pragma unroll
        for (int off = 16; off > 0; off >>= 1) {
            Zr  += __shfl_xor_sync(0xFFFFFFFFu, Zr,  off);
            Wxr += __shfl_xor_sync(0xFFFFFFFFu, Wxr, off);
            Wyr += __shfl_xor_sync(0xFFFFFFFFu, Wyr, off);
            Wzr += __shfl_xor_sync(0xFFFFFFFFu, Wzr, off);
        }

        if (lane == 0) {
            const int ir = blockIdx.x * VSA_ROWS + warp;
            const float qxr = qb[ir * 3 + 0] - mqx;
            const float qyr = qb[ir * 3 + 1] - mqy;
            const float qzr = qb[ir * 3 + 2] - mqz;
            // T' = q x W (= c1 * T);  u = cross(T, v_c) / (Z * N)
            const float Tx = fmaf(qyr, Wzr, -qzr * Wyr);
            const float Ty = fmaf(qzr, Wxr, -qxr * Wzr);
            const float Tz = fmaf(qxr, Wyr, -qyr * Wxr);
            const float vx = vb[ir * 3 + 0] - mvx;
            const float vy = vb[ir * 3 + 1] - mvy;
            const float vz = vb[ir * 3 + 2] - mvz;
            const float inv = 1.0f / (Zr * (float)VSA_N * c1);
            float* o = out + ((size_t)b * VSA_N + ir) * 3;
            o[0] = fmaf(Ty, vz, -Tz * vy) * inv;
            o[1] = fmaf(Tz, vx, -Tx * vz) * inv;
            o[2] = fmaf(Tx, vy, -Ty * vx) * inv;
        }
    }
}

// ---------------------------------------------------------------------------
extern "C" void kernel_launch(void* const* d_in, const int* in_sizes, int n_in,
                              void* d_out, int out_size) {
    const float* q = (const float*)d_in[0];
    const float* k = (const float*)d_in[1];
    const float* v = (const float*)d_in[2];
    float* out = (float*)d_out;

    const int B = out_size / (VSA_N * 3);   // = 4

    dim3 grid(VSA_N / VSA_ROWS, B);         // (64, 4) = 256 blocks
    vsa_fused_kernel<<<grid, VSA_BLK>>>(q, k, v, out);
}